// round 1
// baseline (speedup 1.0000x reference)
#include <cuda_runtime.h>

// Problem constants
#define B_ROWS 16
#define NCOL 2048
#define M 4096          // B_ROWS*NCOL/8 flat rows
#define D 8
#define NC 65536
#define ROWS_PER_M 256  // NCOL/D  (flat rows per batch row)

// Argmin kernel tunables
#define ROWS_PER_BLOCK 32
#define R_PER_THREAD 4
#define CT 32           // code lanes per row-group (one warp)
#define RT 8            // row groups  (CT*RT = 256 threads)
#define NSEG 2
#define SEG_CODES (NC / NSEG)  // 32768
#define TILE 512               // codes staged in shared per iteration

// Scratch (no allocations allowed)
__device__ float g_scale[B_ROWS];
__device__ float g_cnorm[NC];
__device__ unsigned long long g_key[M];   // (mapped_dist<<32) | idx
__device__ float g_sums[NC * D];
__device__ float g_counts[NC];

// ---------------------------------------------------------------------------
// Kernel 1: per-batch-row scale = mean(|x|)
// ---------------------------------------------------------------------------
__global__ void k_scale(const float* __restrict__ x) {
    __shared__ float sh[256];
    int b = blockIdx.x;
    const float* row = x + b * NCOL;
    float s = 0.f;
    for (int i = threadIdx.x; i < NCOL; i += blockDim.x) s += fabsf(row[i]);
    sh[threadIdx.x] = s;
    __syncthreads();
    for (int off = 128; off > 0; off >>= 1) {
        if (threadIdx.x < off) sh[threadIdx.x] += sh[threadIdx.x + off];
        __syncthreads();
    }
    if (threadIdx.x == 0) g_scale[b] = sh[0] * (1.0f / NCOL);
}

// ---------------------------------------------------------------------------
// Kernel 2: codebook squared norms
// ---------------------------------------------------------------------------
__global__ void k_cnorm(const float* __restrict__ cb) {
    int c = blockIdx.x * blockDim.x + threadIdx.x;
    if (c < NC) {
        const float4* p = (const float4*)(cb + c * D);
        float4 a = p[0], b4 = p[1];
        g_cnorm[c] = a.x * a.x + a.y * a.y + a.z * a.z + a.w * a.w +
                     b4.x * b4.x + b4.y * b4.y + b4.z * b4.z + b4.w * b4.w;
    }
}

// ---------------------------------------------------------------------------
// Kernel 3: zero scratch / init keys
// ---------------------------------------------------------------------------
__global__ void k_init() {
    int t = blockIdx.x * blockDim.x + threadIdx.x;
    if (t < NC * D) g_sums[t] = 0.f;
    if (t < NC) g_counts[t] = 0.f;
    if (t < M) g_key[t] = 0xFFFFFFFFFFFFFFFFull;
}

// ---------------------------------------------------------------------------
// Kernel 4: argmin over codes.  grid = (M/ROWS_PER_BLOCK, NSEG)
// Each block: 32 rows x one code segment. Shared tile holds -2*c (transposed,
// dim-major -> conflict-free LDS) and |c|^2.  Cross-block combine via
// atomicMin on monotone-mapped (dist, idx) key (tie -> lowest idx, matching
// jnp.argmin "first" semantics).
// ---------------------------------------------------------------------------
__global__ void __launch_bounds__(CT * RT) k_argmin(const float* __restrict__ x,
                                                    const float* __restrict__ cb) {
    __shared__ float sh_s[D][TILE];  // -2 * codebook[j][c]
    __shared__ float sh_cn[TILE];

    int row0 = blockIdx.x * ROWS_PER_BLOCK;
    int segBase = blockIdx.y * SEG_CODES;
    int ct = threadIdx.x & (CT - 1);
    int rt = threadIdx.x >> 5;

    // Load my rows (scaled)
    float f[R_PER_THREAD][D];
    int myrow0 = row0 + rt * R_PER_THREAD;
#pragma unroll
    for (int r = 0; r < R_PER_THREAD; r++) {
        int m = myrow0 + r;
        float inv = 1.0f / g_scale[m / ROWS_PER_M];
        const float* xr = x + m * D;
#pragma unroll
        for (int j = 0; j < D; j++) f[r][j] = xr[j] * inv;
    }

    float dmin[R_PER_THREAD];
    int imin[R_PER_THREAD];
#pragma unroll
    for (int r = 0; r < R_PER_THREAD; r++) {
        dmin[r] = 3.4e38f;
        imin[r] = 0;
    }

    for (int t0 = 0; t0 < SEG_CODES; t0 += TILE) {
        __syncthreads();
        // Stage TILE codes: transpose + scale by -2 on the fly
        for (int q = threadIdx.x; q < TILE * 2; q += CT * RT) {
            int c = q >> 1;
            int half = q & 1;
            float4 v = *(const float4*)(cb + (size_t)(segBase + t0 + c) * D + half * 4);
            sh_s[half * 4 + 0][c] = -2.f * v.x;
            sh_s[half * 4 + 1][c] = -2.f * v.y;
            sh_s[half * 4 + 2][c] = -2.f * v.z;
            sh_s[half * 4 + 3][c] = -2.f * v.w;
        }
        for (int q = threadIdx.x; q < TILE; q += CT * RT)
            sh_cn[q] = g_cnorm[segBase + t0 + q];
        __syncthreads();

        int kBase = segBase + t0;
        for (int k = ct; k < TILE; k += CT) {
            float s0 = sh_s[0][k], s1 = sh_s[1][k], s2 = sh_s[2][k], s3 = sh_s[3][k];
            float s4 = sh_s[4][k], s5 = sh_s[5][k], s6 = sh_s[6][k], s7 = sh_s[7][k];
            float cn = sh_cn[k];
            int gidx = kBase + k;
#pragma unroll
            for (int r = 0; r < R_PER_THREAD; r++) {
                float d = cn;
                d = fmaf(f[r][0], s0, d);
                d = fmaf(f[r][1], s1, d);
                d = fmaf(f[r][2], s2, d);
                d = fmaf(f[r][3], s3, d);
                d = fmaf(f[r][4], s4, d);
                d = fmaf(f[r][5], s5, d);
                d = fmaf(f[r][6], s6, d);
                d = fmaf(f[r][7], s7, d);
                if (d < dmin[r]) {  // strict < keeps earliest (lowest) idx in-thread
                    dmin[r] = d;
                    imin[r] = gidx;
                }
            }
        }
    }

    // Warp reduction across the 32 code lanes (whole warp shares the same rows)
#pragma unroll
    for (int r = 0; r < R_PER_THREAD; r++) {
        float d = dmin[r];
        int i = imin[r];
        for (int off = 16; off > 0; off >>= 1) {
            float d2 = __shfl_down_sync(0xffffffffu, d, off);
            int i2 = __shfl_down_sync(0xffffffffu, i, off);
            if (d2 < d || (d2 == d && i2 < i)) {
                d = d2;
                i = i2;
            }
        }
        if (ct == 0) {
            unsigned int ud = __float_as_uint(d);
            ud = (ud & 0x80000000u) ? ~ud : (ud | 0x80000000u);  // monotone map
            unsigned long long key = ((unsigned long long)ud << 32) | (unsigned int)i;
            atomicMin(&g_key[myrow0 + r], key);
        }
    }
}

// ---------------------------------------------------------------------------
// Kernel 5: scatter segment sums/counts
// ---------------------------------------------------------------------------
__global__ void k_scatter(const float* __restrict__ x) {
    int m = blockIdx.x * blockDim.x + threadIdx.x;
    if (m >= M) return;
    int idx = (int)(g_key[m] & 0xFFFFFFFFu);
    float inv = 1.0f / g_scale[m / ROWS_PER_M];
    atomicAdd(&g_counts[idx], 1.f);
    const float* xr = x + m * D;
#pragma unroll
    for (int j = 0; j < D; j++) atomicAdd(&g_sums[idx * D + j], xr[j] * inv);
}

// ---------------------------------------------------------------------------
// Kernel 6: gather output = scale * new_codebook[idx]
// ---------------------------------------------------------------------------
__global__ void k_gather(float* __restrict__ out) {
    int t = blockIdx.x * blockDim.x + threadIdx.x;
    if (t >= M * D) return;
    int m = t >> 3;
    int j = t & 7;
    int idx = (int)(g_key[m] & 0xFFFFFFFFu);
    float cnt = g_counts[idx];
    cnt = cnt < 1.f ? 1.f : cnt;
    out[t] = g_scale[m / ROWS_PER_M] * (g_sums[idx * D + j] / cnt);
}

// ---------------------------------------------------------------------------
extern "C" void kernel_launch(void* const* d_in, const int* in_sizes, int n_in,
                              void* d_out, int out_size) {
    const float* x = (const float*)d_in[0];
    const float* cb = (const float*)d_in[1];
    if (n_in >= 2 && in_sizes[0] > in_sizes[1]) {  // defensive: x is the smaller tensor
        x = (const float*)d_in[1];
        cb = (const float*)d_in[0];
    }
    float* out = (float*)d_out;

    k_scale<<<B_ROWS, 256>>>(x);
    k_cnorm<<<NC / 256, 256>>>(cb);
    k_init<<<(NC * D + 255) / 256, 256>>>();
    dim3 grid(M / ROWS_PER_BLOCK, NSEG);
    k_argmin<<<grid, CT * RT>>>(x, cb);
    k_scatter<<<(M + 255) / 256, 256>>>(x);
    k_gather<<<(M * D + 255) / 256, 256>>>(out);
}